// round 11
// baseline (speedup 1.0000x reference)
#include <cuda_runtime.h>
#include <cuda_fp16.h>
#include <stdint.h>

#define NMAX 100000
#define EMAX 3200000
#define H1 32
#define H2 16
#define IND 128
#define CAP 128            // slots per node; Poisson(32) tail @128 ~ 0
#define CAP_SHIFT 7

typedef unsigned long long u64;

// ---------------- scratch (device globals; no allocation allowed) ----------------
__device__ int     g_cnt[NMAX];
__device__ float   g_dinv[NMAX];
__device__ u64     g_slot[(size_t)NMAX * CAP];   // packed {w(f32)<<32 | src}
__device__ __half2 g_xw1h[NMAX * H1 / 2];        // dinv-prescaled x@W1, fp16
__device__ float   g_h[NMAX * H1];               // post layer-1 (relu), fp32
__device__ __half2 g_hw2h[NMAX * H2 / 2];        // dinv-prescaled h@W2, fp16

// ---------------- init ----------------
__global__ void zero_kernel(int n4) {
    int i = blockIdx.x * blockDim.x + threadIdx.x;
    if (i < n4) reinterpret_cast<int4*>(g_cnt)[i] = make_int4(0, 0, 0, 0);
}

// ---------------- single-pass scatter: count + place {w, src} ----------------
__global__ void scatter_kernel(const int* __restrict__ idx,
                               const float* __restrict__ w, int E) {
    int t = blockIdx.x * blockDim.x + threadIdx.x;
    int e = t * 2;
    if (e >= E) return;
    int2   s  = *reinterpret_cast<const int2*>(&idx[e]);
    int2   d  = *reinterpret_cast<const int2*>(&idx[E + e]);
    float2 wv = *reinterpret_cast<const float2*>(&w[e]);
    {
        int pos = atomicAdd(&g_cnt[d.x], 1);
        if (pos < CAP)
            g_slot[((size_t)d.x << CAP_SHIFT) + pos] =
                ((u64)(unsigned)__float_as_int(wv.x) << 32) | (unsigned)s.x;
    }
    if (e + 1 < E) {
        int pos = atomicAdd(&g_cnt[d.y], 1);
        if (pos < CAP)
            g_slot[((size_t)d.y << CAP_SHIFT) + pos] =
                ((u64)(unsigned)__float_as_int(wv.y) << 32) | (unsigned)s.y;
    }
}

// ---------------- deg reduce -> dinv (warp per node) ----------------
__global__ void dinv_kernel(int n) {
    int v = (blockIdx.x * blockDim.x + threadIdx.x) >> 5;
    int lane = threadIdx.x & 31;
    if (v >= n) return;
    int cnt = min(g_cnt[v], CAP);
    size_t base = (size_t)v << CAP_SHIFT;
    float s = 0.f;
    for (int i = lane; i < cnt; i += 32) {
        u64 p = __ldg(&g_slot[base + i]);
        s += __int_as_float((int)(p >> 32));
    }
    #pragma unroll
    for (int m = 16; m; m >>= 1) s += __shfl_xor_sync(0xffffffffu, s, m);
    if (lane == 0) g_dinv[v] = rsqrtf(s + 1.0f);
}

// ---------------- GEMM1: warp = 8 rows x 4 colgroups; LDS broadcast-friendly ----------
__global__ void __launch_bounds__(256) gemm1_kernel(const float* __restrict__ X,
                                                    const float* __restrict__ W, int n) {
    __shared__ float Ws[IND * H1];
    for (int i = threadIdx.x; i < IND * H1; i += blockDim.x) Ws[i] = W[i];
    __syncthreads();
    int gw   = (blockIdx.x * blockDim.x + threadIdx.x) >> 5;   // global warp
    int lane = threadIdx.x & 31;
    int rowg = lane >> 2;     // 0..7
    int colg = lane & 3;      // 0..3 -> 8 cols each
    int r = gw * 8 + rowg;
    if (r >= n) return;
    float acc[8];
    #pragma unroll
    for (int j = 0; j < 8; j++) acc[j] = 0.f;
    const float4* X4 = reinterpret_cast<const float4*>(X) + (size_t)r * (IND / 4);
    int cbase = colg * 8;
    #pragma unroll 4
    for (int k4 = 0; k4 < IND / 4; k4++) {
        float4 xv = __ldg(&X4[k4]);   // 4 lanes/row share address -> coalesced
        float xk[4] = {xv.x, xv.y, xv.z, xv.w};
        #pragma unroll
        for (int kk = 0; kk < 4; kk++) {
            const float4* wr =
                reinterpret_cast<const float4*>(&Ws[(k4 * 4 + kk) * H1 + cbase]);
            float xs = xk[kk];
            float4 w0 = wr[0];
            float4 w1 = wr[1];    // 64B distinct per warp -> 1 crossbar phase
            acc[0] = fmaf(xs, w0.x, acc[0]);
            acc[1] = fmaf(xs, w0.y, acc[1]);
            acc[2] = fmaf(xs, w0.z, acc[2]);
            acc[3] = fmaf(xs, w0.w, acc[3]);
            acc[4] = fmaf(xs, w1.x, acc[4]);
            acc[5] = fmaf(xs, w1.y, acc[5]);
            acc[6] = fmaf(xs, w1.z, acc[6]);
            acc[7] = fmaf(xs, w1.w, acc[7]);
        }
    }
    float di = g_dinv[r];
    __half2* O = g_xw1h + (size_t)r * (H1 / 2) + colg * 4;
    #pragma unroll
    for (int j = 0; j < 4; j++)
        O[j] = __floats2half2_rn(acc[2 * j] * di, acc[2 * j + 1] * di);
}

// ---------------- agg layer 1: warp/node, 2 subs x 16 lanes x half2, relu ----------------
__global__ void agg32_kernel(const float* __restrict__ b1, int n) {
    int v = (blockIdx.x * blockDim.x + threadIdx.x) >> 5;
    int lane = threadIdx.x & 31;
    if (v >= n) return;
    int sub = lane >> 4;          // 0/1: alternate edges
    int li  = lane & 15;          // half2 column
    size_t base = (size_t)v << CAP_SHIFT;
    int cnt = min(g_cnt[v], CAP);
    size_t end = base + cnt;
    float2 acc = make_float2(0.f, 0.f);
    for (size_t e = base + sub; e < end; e += 2) {
        u64 p = __ldg(&g_slot[e]);
        float wv = __int_as_float((int)(p >> 32));
        int src = (int)(p & 0xffffffffu);
        float2 f = __half22float2(__ldg(&g_xw1h[(size_t)src * 16 + li]));
        acc.x = fmaf(wv, f.x, acc.x);
        acc.y = fmaf(wv, f.y, acc.y);
    }
    acc.x += __shfl_xor_sync(0xffffffffu, acc.x, 16);
    acc.y += __shfl_xor_sync(0xffffffffu, acc.y, 16);
    float di = g_dinv[v];
    float2 sf = __half22float2(__ldg(&g_xw1h[(size_t)v * 16 + li]));
    float2 r;
    r.x = fmaxf(fmaf(di, acc.x + sf.x, __ldg(&b1[2 * li])),     0.f);
    r.y = fmaxf(fmaf(di, acc.y + sf.y, __ldg(&b1[2 * li + 1])), 0.f);
    if (sub == 0)
        reinterpret_cast<float2*>(g_h)[(size_t)v * 16 + li] = r;
}

// ---------------- GEMM2: hw2h[r] = fp16( dinv[r] * (h[r] @ W2) ) ----------------
__global__ void gemm2_kernel(const float* __restrict__ W, int n) {
    __shared__ float Ws[H1 * H2];
    for (int i = threadIdx.x; i < H1 * H2; i += blockDim.x) Ws[i] = W[i];
    __syncthreads();
    int r = blockIdx.x * blockDim.x + threadIdx.x;
    if (r >= n) return;
    float acc[H2];
    #pragma unroll
    for (int j = 0; j < H2; j++) acc[j] = 0.f;
    const float4* X4 = reinterpret_cast<const float4*>(g_h) + (size_t)r * (H1 / 4);
    #pragma unroll
    for (int k4 = 0; k4 < H1 / 4; k4++) {
        float4 xv = X4[k4];
        float xk[4] = {xv.x, xv.y, xv.z, xv.w};
        #pragma unroll
        for (int kk = 0; kk < 4; kk++) {
            const float4* wr = reinterpret_cast<const float4*>(&Ws[(k4 * 4 + kk) * H2]);
            float xs = xk[kk];
            #pragma unroll
            for (int j4 = 0; j4 < H2 / 4; j4++) {
                float4 wv = wr[j4];
                acc[4 * j4 + 0] = fmaf(xs, wv.x, acc[4 * j4 + 0]);
                acc[4 * j4 + 1] = fmaf(xs, wv.y, acc[4 * j4 + 1]);
                acc[4 * j4 + 2] = fmaf(xs, wv.z, acc[4 * j4 + 2]);
                acc[4 * j4 + 3] = fmaf(xs, wv.w, acc[4 * j4 + 3]);
            }
        }
    }
    float di = g_dinv[r];
    __half2* O = g_hw2h + (size_t)r * (H2 / 2);
    #pragma unroll
    for (int j = 0; j < H2 / 2; j++)
        O[j] = __floats2half2_rn(acc[2 * j] * di, acc[2 * j + 1] * di);
}

// ---------------- agg layer 2: warp/node, 4 subs x 8 lanes x half2 ----------------
__global__ void agg16_kernel(const float* __restrict__ b2, float* __restrict__ out, int n) {
    int v = (blockIdx.x * blockDim.x + threadIdx.x) >> 5;
    int lane = threadIdx.x & 31;
    if (v >= n) return;
    int sub = lane >> 3;          // 0..3: alternate edges
    int li  = lane & 7;           // half2 column
    size_t base = (size_t)v << CAP_SHIFT;
    int cnt = min(g_cnt[v], CAP);
    size_t end = base + cnt;
    float2 acc = make_float2(0.f, 0.f);
    for (size_t e = base + sub; e < end; e += 4) {
        u64 p = __ldg(&g_slot[e]);
        float wv = __int_as_float((int)(p >> 32));
        int src = (int)(p & 0xffffffffu);
        float2 f = __half22float2(__ldg(&g_hw2h[(size_t)src * 8 + li]));
        acc.x = fmaf(wv, f.x, acc.x);
        acc.y = fmaf(wv, f.y, acc.y);
    }
    acc.x += __shfl_xor_sync(0xffffffffu, acc.x, 8);
    acc.y += __shfl_xor_sync(0xffffffffu, acc.y, 8);
    acc.x += __shfl_xor_sync(0xffffffffu, acc.x, 16);
    acc.y += __shfl_xor_sync(0xffffffffu, acc.y, 16);
    float di = g_dinv[v];
    float2 sf = __half22float2(__ldg(&g_hw2h[(size_t)v * 8 + li]));
    float2 r;
    r.x = fmaf(di, acc.x + sf.x, __ldg(&b2[2 * li]));
    r.y = fmaf(di, acc.y + sf.y, __ldg(&b2[2 * li + 1]));
    if (lane < 8)
        reinterpret_cast<float2*>(out)[(size_t)v * 8 + li] = r;
}

// ---------------- launch ----------------
extern "C" void kernel_launch(void* const* d_in, const int* in_sizes, int n_in,
                              void* d_out, int out_size) {
    const float* x   = (const float*)d_in[0];
    const int*   ei  = (const int*)d_in[1];
    const float* ew  = (const float*)d_in[2];
    const float* W1  = (const float*)d_in[3];
    const float* b1  = (const float*)d_in[4];
    const float* W2  = (const float*)d_in[5];
    const float* b2  = (const float*)d_in[6];
    float*       out = (float*)d_out;

    int E = in_sizes[2];
    int n = in_sizes[0] / IND;

    int n4 = (n + 3) / 4;
    int nb_n = (n + 255) / 256;
    int nb_e2 = ((E + 1) / 2 + 255) / 256;
    int nb_w = (n * 32 + 255) / 256;
    int nwarps_g1 = (n + 7) / 8;
    int nb_g1 = (nwarps_g1 * 32 + 255) / 256;

    zero_kernel<<<(n4 + 255) / 256, 256>>>(n4);
    scatter_kernel<<<nb_e2, 256>>>(ei, ew, E);
    dinv_kernel<<<nb_w, 256>>>(n);
    gemm1_kernel<<<nb_g1, 256>>>(x, W1, n);
    agg32_kernel<<<nb_w, 256>>>(b1, n);
    gemm2_kernel<<<nb_n, 256>>>(W2, n);
    agg16_kernel<<<nb_w, 256>>>(b2, out, n);
}

// round 12
// speedup vs baseline: 1.0185x; 1.0185x over previous
#include <cuda_runtime.h>
#include <cuda_fp16.h>
#include <stdint.h>

#define NMAX 100000
#define EMAX 3200000
#define H1 32
#define H2 16
#define IND 128
#define CAP 128            // slots per node; Poisson(32) tail @128 ~ 0
#define CAP_SHIFT 7
#define G1_ROWS 32         // rows per gemm1 block
#define XPAD 132           // 128 + 4 floats padding (conflict-free)

typedef unsigned long long u64;

// ---------------- scratch (device globals; no allocation allowed) ----------------
__device__ int     g_cnt[NMAX];
__device__ float   g_dinv[NMAX];
__device__ u64     g_slot[(size_t)NMAX * CAP];   // packed {w(f32)<<32 | src}
__device__ __half2 g_xw1h[NMAX * H1 / 2];        // dinv-prescaled x@W1, fp16
__device__ float   g_h[NMAX * H1];               // post layer-1 (relu), fp32
__device__ __half2 g_hw2h[NMAX * H2 / 2];        // dinv-prescaled h@W2, fp16

// ---------------- init ----------------
__global__ void zero_kernel(int n4) {
    int i = blockIdx.x * blockDim.x + threadIdx.x;
    if (i < n4) reinterpret_cast<int4*>(g_cnt)[i] = make_int4(0, 0, 0, 0);
}

// ---------------- single-pass scatter: count + place {w, src} ----------------
__global__ void scatter_kernel(const int* __restrict__ idx,
                               const float* __restrict__ w, int E) {
    int t = blockIdx.x * blockDim.x + threadIdx.x;
    int e = t * 2;
    if (e >= E) return;
    int2   s  = *reinterpret_cast<const int2*>(&idx[e]);
    int2   d  = *reinterpret_cast<const int2*>(&idx[E + e]);
    float2 wv = *reinterpret_cast<const float2*>(&w[e]);
    {
        int pos = atomicAdd(&g_cnt[d.x], 1);
        if (pos < CAP)
            g_slot[((size_t)d.x << CAP_SHIFT) + pos] =
                ((u64)(unsigned)__float_as_int(wv.x) << 32) | (unsigned)s.x;
    }
    if (e + 1 < E) {
        int pos = atomicAdd(&g_cnt[d.y], 1);
        if (pos < CAP)
            g_slot[((size_t)d.y << CAP_SHIFT) + pos] =
                ((u64)(unsigned)__float_as_int(wv.y) << 32) | (unsigned)s.y;
    }
}

// ---------------- deg reduce -> dinv (warp per node) ----------------
__global__ void dinv_kernel(int n) {
    int v = (blockIdx.x * blockDim.x + threadIdx.x) >> 5;
    int lane = threadIdx.x & 31;
    if (v >= n) return;
    int cnt = min(g_cnt[v], CAP);
    size_t base = (size_t)v << CAP_SHIFT;
    float s = 0.f;
    for (int i = lane; i < cnt; i += 32) {
        u64 p = __ldg(&g_slot[base + i]);
        s += __int_as_float((int)(p >> 32));
    }
    #pragma unroll
    for (int m = 16; m; m >>= 1) s += __shfl_xor_sync(0xffffffffu, s, m);
    if (lane == 0) g_dinv[v] = rsqrtf(s + 1.0f);
}

// ---------------- GEMM1: smem-staged tile; coalesced X, conflict-free compute ----------
__global__ void __launch_bounds__(256) gemm1_kernel(const float* __restrict__ X,
                                                    const float* __restrict__ W, int n) {
    __shared__ float Ws[IND * H1];          // 16 KB
    __shared__ float Xs[G1_ROWS * XPAD];    // 16.9 KB, padded rows
    int tid = threadIdx.x;
    for (int i = tid; i < IND * H1 / 4; i += blockDim.x)
        reinterpret_cast<float4*>(Ws)[i] = reinterpret_cast<const float4*>(W)[i];

    int rbase = blockIdx.x * G1_ROWS;
    // coalesced X tile load: i = row*32 + k4 (one warp covers one full 512B row)
    for (int i = tid; i < G1_ROWS * (IND / 4); i += blockDim.x) {
        int row = i >> 5;
        int k4  = i & 31;
        int gr = rbase + row;
        float4 v = (gr < n) ? __ldg(reinterpret_cast<const float4*>(X) +
                                    (size_t)gr * (IND / 4) + k4)
                            : make_float4(0.f, 0.f, 0.f, 0.f);
        *reinterpret_cast<float4*>(&Xs[row * XPAD + k4 * 4]) = v;
    }
    __syncthreads();

    int row  = tid >> 3;      // 0..31
    int colg = tid & 7;       // 4 cols each
    int gr = rbase + row;
    if (gr >= n) return;
    float acc0 = 0.f, acc1 = 0.f, acc2 = 0.f, acc3 = 0.f;
    const float4* xr = reinterpret_cast<const float4*>(&Xs[row * XPAD]);
    #pragma unroll 8
    for (int k4 = 0; k4 < IND / 4; k4++) {
        float4 xv = xr[k4];
        float xk[4] = {xv.x, xv.y, xv.z, xv.w};
        #pragma unroll
        for (int kk = 0; kk < 4; kk++) {
            float4 wv = reinterpret_cast<const float4*>(Ws)[(k4 * 4 + kk) * 8 + colg];
            float xs = xk[kk];
            acc0 = fmaf(xs, wv.x, acc0);
            acc1 = fmaf(xs, wv.y, acc1);
            acc2 = fmaf(xs, wv.z, acc2);
            acc3 = fmaf(xs, wv.w, acc3);
        }
    }
    float di = g_dinv[gr];
    __half2 h0 = __floats2half2_rn(acc0 * di, acc1 * di);
    __half2 h1 = __floats2half2_rn(acc2 * di, acc3 * di);
    // 8-byte store of 2 half2
    uint2 pk;
    pk.x = *reinterpret_cast<unsigned*>(&h0);
    pk.y = *reinterpret_cast<unsigned*>(&h1);
    *reinterpret_cast<uint2*>(&g_xw1h[(size_t)gr * 16 + colg * 2]) = pk;
}

// ---------------- agg layer 1: warp/node, 2 subs x 16 lanes x half2, relu ----------------
__global__ void agg32_kernel(const float* __restrict__ b1, int n) {
    int v = (blockIdx.x * blockDim.x + threadIdx.x) >> 5;
    int lane = threadIdx.x & 31;
    if (v >= n) return;
    int sub = lane >> 4;          // 0/1: alternate edges
    int li  = lane & 15;          // half2 column
    size_t base = (size_t)v << CAP_SHIFT;
    int cnt = min(g_cnt[v], CAP);
    size_t end = base + cnt;
    float2 acc = make_float2(0.f, 0.f);
    for (size_t e = base + sub; e < end; e += 2) {
        u64 p = __ldg(&g_slot[e]);
        float wv = __int_as_float((int)(p >> 32));
        int src = (int)(p & 0xffffffffu);
        float2 f = __half22float2(__ldg(&g_xw1h[(size_t)src * 16 + li]));
        acc.x = fmaf(wv, f.x, acc.x);
        acc.y = fmaf(wv, f.y, acc.y);
    }
    acc.x += __shfl_xor_sync(0xffffffffu, acc.x, 16);
    acc.y += __shfl_xor_sync(0xffffffffu, acc.y, 16);
    float di = g_dinv[v];
    float2 sf = __half22float2(__ldg(&g_xw1h[(size_t)v * 16 + li]));
    float2 r;
    r.x = fmaxf(fmaf(di, acc.x + sf.x, __ldg(&b1[2 * li])),     0.f);
    r.y = fmaxf(fmaf(di, acc.y + sf.y, __ldg(&b1[2 * li + 1])), 0.f);
    if (sub == 0)
        reinterpret_cast<float2*>(g_h)[(size_t)v * 16 + li] = r;
}

// ---------------- GEMM2: hw2h[r] = fp16( dinv[r] * (h[r] @ W2) ) ----------------
__global__ void gemm2_kernel(const float* __restrict__ W, int n) {
    __shared__ float Ws[H1 * H2];
    for (int i = threadIdx.x; i < H1 * H2; i += blockDim.x) Ws[i] = W[i];
    __syncthreads();
    int r = blockIdx.x * blockDim.x + threadIdx.x;
    if (r >= n) return;
    float acc[H2];
    #pragma unroll
    for (int j = 0; j < H2; j++) acc[j] = 0.f;
    const float4* X4 = reinterpret_cast<const float4*>(g_h) + (size_t)r * (H1 / 4);
    #pragma unroll
    for (int k4 = 0; k4 < H1 / 4; k4++) {
        float4 xv = X4[k4];
        float xk[4] = {xv.x, xv.y, xv.z, xv.w};
        #pragma unroll
        for (int kk = 0; kk < 4; kk++) {
            const float4* wr = reinterpret_cast<const float4*>(&Ws[(k4 * 4 + kk) * H2]);
            float xs = xk[kk];
            #pragma unroll
            for (int j4 = 0; j4 < H2 / 4; j4++) {
                float4 wv = wr[j4];
                acc[4 * j4 + 0] = fmaf(xs, wv.x, acc[4 * j4 + 0]);
                acc[4 * j4 + 1] = fmaf(xs, wv.y, acc[4 * j4 + 1]);
                acc[4 * j4 + 2] = fmaf(xs, wv.z, acc[4 * j4 + 2]);
                acc[4 * j4 + 3] = fmaf(xs, wv.w, acc[4 * j4 + 3]);
            }
        }
    }
    float di = g_dinv[r];
    __half2* O = g_hw2h + (size_t)r * (H2 / 2);
    #pragma unroll
    for (int j = 0; j < H2 / 2; j++)
        O[j] = __floats2half2_rn(acc[2 * j] * di, acc[2 * j + 1] * di);
}

// ---------------- agg layer 2: warp/node, 4 subs x 8 lanes x half2 ----------------
__global__ void agg16_kernel(const float* __restrict__ b2, float* __restrict__ out, int n) {
    int v = (blockIdx.x * blockDim.x + threadIdx.x) >> 5;
    int lane = threadIdx.x & 31;
    if (v >= n) return;
    int sub = lane >> 3;          // 0..3: alternate edges
    int li  = lane & 7;           // half2 column
    size_t base = (size_t)v << CAP_SHIFT;
    int cnt = min(g_cnt[v], CAP);
    size_t end = base + cnt;
    float2 acc = make_float2(0.f, 0.f);
    for (size_t e = base + sub; e < end; e += 4) {
        u64 p = __ldg(&g_slot[e]);
        float wv = __int_as_float((int)(p >> 32));
        int src = (int)(p & 0xffffffffu);
        float2 f = __half22float2(__ldg(&g_hw2h[(size_t)src * 8 + li]));
        acc.x = fmaf(wv, f.x, acc.x);
        acc.y = fmaf(wv, f.y, acc.y);
    }
    acc.x += __shfl_xor_sync(0xffffffffu, acc.x, 8);
    acc.y += __shfl_xor_sync(0xffffffffu, acc.y, 8);
    acc.x += __shfl_xor_sync(0xffffffffu, acc.x, 16);
    acc.y += __shfl_xor_sync(0xffffffffu, acc.y, 16);
    float di = g_dinv[v];
    float2 sf = __half22float2(__ldg(&g_hw2h[(size_t)v * 8 + li]));
    float2 r;
    r.x = fmaf(di, acc.x + sf.x, __ldg(&b2[2 * li]));
    r.y = fmaf(di, acc.y + sf.y, __ldg(&b2[2 * li + 1]));
    if (lane < 8)
        reinterpret_cast<float2*>(out)[(size_t)v * 8 + li] = r;
}

// ---------------- launch ----------------
extern "C" void kernel_launch(void* const* d_in, const int* in_sizes, int n_in,
                              void* d_out, int out_size) {
    const float* x   = (const float*)d_in[0];
    const int*   ei  = (const int*)d_in[1];
    const float* ew  = (const float*)d_in[2];
    const float* W1  = (const float*)d_in[3];
    const float* b1  = (const float*)d_in[4];
    const float* W2  = (const float*)d_in[5];
    const float* b2  = (const float*)d_in[6];
    float*       out = (float*)d_out;

    int E = in_sizes[2];
    int n = in_sizes[0] / IND;

    int n4 = (n + 3) / 4;
    int nb_n = (n + 255) / 256;
    int nb_e2 = ((E + 1) / 2 + 255) / 256;
    int nb_w = (n * 32 + 255) / 256;
    int nb_g1 = (n + G1_ROWS - 1) / G1_ROWS;

    zero_kernel<<<(n4 + 255) / 256, 256>>>(n4);
    scatter_kernel<<<nb_e2, 256>>>(ei, ew, E);
    dinv_kernel<<<nb_w, 256>>>(n);
    gemm1_kernel<<<nb_g1, 256>>>(x, W1, n);
    agg32_kernel<<<nb_w, 256>>>(b1, n);
    gemm2_kernel<<<nb_n, 256>>>(W2, n);
    agg16_kernel<<<nb_w, 256>>>(b2, out, n);
}

// round 14
// speedup vs baseline: 1.0263x; 1.0077x over previous
#include <cuda_runtime.h>
#include <cuda_fp16.h>
#include <stdint.h>

#define NMAX 100000
#define EMAX 3200000
#define H1 32
#define H2 16
#define IND 128
#define CAP 128            // slots per node; Poisson(32) tail @128 ~ 0
#define CAP_SHIFT 7
#define G1_ROWS 24         // rows per gemm1 tile
#define G1_THREADS 192
#define XPAD 132           // 128 + 4 floats padding (16B-aligned rows, conflict-free)

typedef unsigned long long u64;

// ---------------- scratch (device globals; no allocation allowed) ----------------
__device__ int     g_cnt[NMAX];
__device__ float   g_dinv[NMAX];
__device__ u64     g_slot[(size_t)NMAX * CAP];   // packed {w(f32)<<32 | src}
__device__ __half2 g_xw1h[NMAX * H1 / 2];        // dinv-prescaled x@W1, fp16
__device__ float   g_h[NMAX * H1];               // post layer-1 (relu), fp32
__device__ __half2 g_hw2h[NMAX * H2 / 2];        // dinv-prescaled h@W2, fp16

// ---------------- init ----------------
__global__ void zero_kernel(int n4) {
    int i = blockIdx.x * blockDim.x + threadIdx.x;
    if (i < n4) reinterpret_cast<int4*>(g_cnt)[i] = make_int4(0, 0, 0, 0);
}

// ---------------- single-pass scatter: count + place {w, src} ----------------
__global__ void scatter_kernel(const int* __restrict__ idx,
                               const float* __restrict__ w, int E) {
    int t = blockIdx.x * blockDim.x + threadIdx.x;
    int e = t * 2;
    if (e >= E) return;
    int2   s  = *reinterpret_cast<const int2*>(&idx[e]);
    int2   d  = *reinterpret_cast<const int2*>(&idx[E + e]);
    float2 wv = *reinterpret_cast<const float2*>(&w[e]);
    {
        int pos = atomicAdd(&g_cnt[d.x], 1);
        if (pos < CAP)
            g_slot[((size_t)d.x << CAP_SHIFT) + pos] =
                ((u64)(unsigned)__float_as_int(wv.x) << 32) | (unsigned)s.x;
    }
    if (e + 1 < E) {
        int pos = atomicAdd(&g_cnt[d.y], 1);
        if (pos < CAP)
            g_slot[((size_t)d.y << CAP_SHIFT) + pos] =
                ((u64)(unsigned)__float_as_int(wv.y) << 32) | (unsigned)s.y;
    }
}

// ---------------- deg reduce -> dinv (warp per node) ----------------
__global__ void dinv_kernel(int n) {
    int v = (blockIdx.x * blockDim.x + threadIdx.x) >> 5;
    int lane = threadIdx.x & 31;
    if (v >= n) return;
    int cnt = min(g_cnt[v], CAP);
    size_t base = (size_t)v << CAP_SHIFT;
    float s = 0.f;
    for (int i = lane; i < cnt; i += 32) {
        u64 p = __ldg(&g_slot[base + i]);
        s += __int_as_float((int)(p >> 32));
    }
    #pragma unroll
    for (int m = 16; m; m >>= 1) s += __shfl_xor_sync(0xffffffffu, s, m);
    if (lane == 0) g_dinv[v] = rsqrtf(s + 1.0f);
}

// ---------------- GEMM1: cp.async double-buffered tile pipeline ----------------
__global__ void __launch_bounds__(G1_THREADS) gemm1_kernel(const float* __restrict__ X,
                                                           const float* __restrict__ W,
                                                           int n, int ntiles) {
    __shared__ float Ws[IND * H1];                 // 16 KB
    __shared__ float Xs[2][G1_ROWS * XPAD];        // 2 x 12.7 KB
    int tid = threadIdx.x;
    for (int i = tid; i < IND * H1 / 4; i += G1_THREADS)
        reinterpret_cast<float4*>(Ws)[i] = reinterpret_cast<const float4*>(W)[i];

    int stride = gridDim.x;
    int t0 = blockIdx.x;

    // --- prefetch helper (inlined): tile -> Xs[buf] via cp.async 16B ---
    #define PREFETCH(tile, pbuf)                                                         \
        {                                                                                \
            _Pragma("unroll")                                                            \
            for (int j = 0; j < 4; j++) {                                                \
                int i = tid + j * G1_THREADS;                                            \
                int row = i >> 5;                                                        \
                int k4  = i & 31;                                                        \
                int gr = (tile) * G1_ROWS + row;                                         \
                if (gr < n) {                                                            \
                    unsigned sa = (unsigned)__cvta_generic_to_shared(                    \
                        &Xs[pbuf][row * XPAD + k4 * 4]);                                 \
                    const float* gp = X + (size_t)gr * IND + k4 * 4;                     \
                    asm volatile("cp.async.cg.shared.global [%0], [%1], 16;"             \
                                 :: "r"(sa), "l"(gp));                                   \
                }                                                                        \
            }                                                                            \
        }

    if (t0 < ntiles) PREFETCH(t0, 0);
    asm volatile("cp.async.commit_group;");

    int buf = 0;
    for (int t = t0; t < ntiles; t += stride) {
        int nxt = t + stride;
        if (nxt < ntiles) {
            PREFETCH(nxt, buf ^ 1);
            asm volatile("cp.async.commit_group;");
            asm volatile("cp.async.wait_group 1;");
        } else {
            asm volatile("cp.async.wait_group 0;");
        }
        __syncthreads();

        int row  = tid >> 3;      // 0..23
        int colg = tid & 7;       // 4 cols each
        int gr = t * G1_ROWS + row;
        if (gr < n) {
            float acc0 = 0.f, acc1 = 0.f, acc2 = 0.f, acc3 = 0.f;
            const float4* xr = reinterpret_cast<const float4*>(&Xs[buf][row * XPAD]);
            #pragma unroll 8
            for (int k4 = 0; k4 < IND / 4; k4++) {
                float4 xv = xr[k4];
                float xk[4] = {xv.x, xv.y, xv.z, xv.w};
                #pragma unroll
                for (int kk = 0; kk < 4; kk++) {
                    float4 wv =
                        reinterpret_cast<const float4*>(Ws)[(k4 * 4 + kk) * 8 + colg];
                    float xs = xk[kk];
                    acc0 = fmaf(xs, wv.x, acc0);
                    acc1 = fmaf(xs, wv.y, acc1);
                    acc2 = fmaf(xs, wv.z, acc2);
                    acc3 = fmaf(xs, wv.w, acc3);
                }
            }
            float di = g_dinv[gr];
            __half2 h0 = __floats2half2_rn(acc0 * di, acc1 * di);
            __half2 h1 = __floats2half2_rn(acc2 * di, acc3 * di);
            uint2 pk;
            pk.x = *reinterpret_cast<unsigned*>(&h0);
            pk.y = *reinterpret_cast<unsigned*>(&h1);
            *reinterpret_cast<uint2*>(&g_xw1h[(size_t)gr * 16 + colg * 2]) = pk;
        }
        buf ^= 1;
        __syncthreads();
    }
    #undef PREFETCH
}

// ---------------- agg layer 1: warp/node, 2 subs x 16 lanes x half2, relu ----------------
__global__ void agg32_kernel(const float* __restrict__ b1, int n) {
    int v = (blockIdx.x * blockDim.x + threadIdx.x) >> 5;
    int lane = threadIdx.x & 31;
    if (v >= n) return;
    int sub = lane >> 4;          // 0/1: alternate edges
    int li  = lane & 15;          // half2 column
    size_t base = (size_t)v << CAP_SHIFT;
    int cnt = min(g_cnt[v], CAP);
    size_t end = base + cnt;
    float2 acc = make_float2(0.f, 0.f);
    for (size_t e = base + sub; e < end; e += 2) {
        u64 p = __ldg(&g_slot[e]);
        float wv = __int_as_float((int)(p >> 32));
        int src = (int)(p & 0xffffffffu);
        float2 f = __half22float2(__ldg(&g_xw1h[(size_t)src * 16 + li]));
        acc.x = fmaf(wv, f.x, acc.x);
        acc.y = fmaf(wv, f.y, acc.y);
    }
    acc.x += __shfl_xor_sync(0xffffffffu, acc.x, 16);
    acc.y += __shfl_xor_sync(0xffffffffu, acc.y, 16);
    float di = g_dinv[v];
    float2 sf = __half22float2(__ldg(&g_xw1h[(size_t)v * 16 + li]));
    float2 r;
    r.x = fmaxf(fmaf(di, acc.x + sf.x, __ldg(&b1[2 * li])),     0.f);
    r.y = fmaxf(fmaf(di, acc.y + sf.y, __ldg(&b1[2 * li + 1])), 0.f);
    if (sub == 0)
        reinterpret_cast<float2*>(g_h)[(size_t)v * 16 + li] = r;
}

// ---------------- GEMM2: hw2h[r] = fp16( dinv[r] * (h[r] @ W2) ) ----------------
__global__ void gemm2_kernel(const float* __restrict__ W, int n) {
    __shared__ float Ws[H1 * H2];
    for (int i = threadIdx.x; i < H1 * H2; i += blockDim.x) Ws[i] = W[i];
    __syncthreads();
    int r = blockIdx.x * blockDim.x + threadIdx.x;
    if (r >= n) return;
    float acc[H2];
    #pragma unroll
    for (int j = 0; j < H2; j++) acc[j] = 0.f;
    const float4* X4 = reinterpret_cast<const float4*>(g_h) + (size_t)r * (H1 / 4);
    #pragma unroll
    for (int k4 = 0; k4 < H1 / 4; k4++) {
        float4 xv = X4[k4];
        float xk[4] = {xv.x, xv.y, xv.z, xv.w};
        #pragma unroll
        for (int kk = 0; kk < 4; kk++) {
            const float4* wr = reinterpret_cast<const float4*>(&Ws[(k4 * 4 + kk) * H2]);
            float xs = xk[kk];
            #pragma unroll
            for (int j4 = 0; j4 < H2 / 4; j4++) {
                float4 wv = wr[j4];
                acc[4 * j4 + 0] = fmaf(xs, wv.x, acc[4 * j4 + 0]);
                acc[4 * j4 + 1] = fmaf(xs, wv.y, acc[4 * j4 + 1]);
                acc[4 * j4 + 2] = fmaf(xs, wv.z, acc[4 * j4 + 2]);
                acc[4 * j4 + 3] = fmaf(xs, wv.w, acc[4 * j4 + 3]);
            }
        }
    }
    float di = g_dinv[r];
    __half2* O = g_hw2h + (size_t)r * (H2 / 2);
    #pragma unroll
    for (int j = 0; j < H2 / 2; j++)
        O[j] = __floats2half2_rn(acc[2 * j] * di, acc[2 * j + 1] * di);
}

// ---------------- agg layer 2: warp/node, 4 subs x 8 lanes x half2 ----------------
__global__ void agg16_kernel(const float* __restrict__ b2, float* __restrict__ out, int n) {
    int v = (blockIdx.x * blockDim.x + threadIdx.x) >> 5;
    int lane = threadIdx.x & 31;
    if (v >= n) return;
    int sub = lane >> 3;          // 0..3: alternate edges
    int li  = lane & 7;           // half2 column
    size_t base = (size_t)v << CAP_SHIFT;
    int cnt = min(g_cnt[v], CAP);
    size_t end = base + cnt;
    float2 acc = make_float2(0.f, 0.f);
    for (size_t e = base + sub; e < end; e += 4) {
        u64 p = __ldg(&g_slot[e]);
        float wv = __int_as_float((int)(p >> 32));
        int src = (int)(p & 0xffffffffu);
        float2 f = __half22float2(__ldg(&g_hw2h[(size_t)src * 8 + li]));
        acc.x = fmaf(wv, f.x, acc.x);
        acc.y = fmaf(wv, f.y, acc.y);
    }
    acc.x += __shfl_xor_sync(0xffffffffu, acc.x, 8);
    acc.y += __shfl_xor_sync(0xffffffffu, acc.y, 8);
    acc.x += __shfl_xor_sync(0xffffffffu, acc.x, 16);
    acc.y += __shfl_xor_sync(0xffffffffu, acc.y, 16);
    float di = g_dinv[v];
    float2 sf = __half22float2(__ldg(&g_hw2h[(size_t)v * 8 + li]));
    float2 r;
    r.x = fmaf(di, acc.x + sf.x, __ldg(&b2[2 * li]));
    r.y = fmaf(di, acc.y + sf.y, __ldg(&b2[2 * li + 1]));
    if (lane < 8)
        reinterpret_cast<float2*>(out)[(size_t)v * 8 + li] = r;
}

// ---------------- launch ----------------
extern "C" void kernel_launch(void* const* d_in, const int* in_sizes, int n_in,
                              void* d_out, int out_size) {
    const float* x   = (const float*)d_in[0];
    const int*   ei  = (const int*)d_in[1];
    const float* ew  = (const float*)d_in[2];
    const float* W1  = (const float*)d_in[3];
    const float* b1  = (const float*)d_in[4];
    const float* W2  = (const float*)d_in[5];
    const float* b2  = (const float*)d_in[6];
    float*       out = (float*)d_out;

    int E = in_sizes[2];
    int n = in_sizes[0] / IND;

    int n4 = (n + 3) / 4;
    int nb_n = (n + 255) / 256;
    int nb_e2 = ((E + 1) / 2 + 255) / 256;
    int nb_w = (n * 32 + 255) / 256;
    int ntiles = (n + G1_ROWS - 1) / G1_ROWS;
    int nb_g1 = ntiles < 740 ? ntiles : 740;   // ~5 blocks/SM (smem-limited)

    zero_kernel<<<(n4 + 255) / 256, 256>>>(n4);
    scatter_kernel<<<nb_e2, 256>>>(ei, ew, E);
    dinv_kernel<<<nb_w, 256>>>(n);
    gemm1_kernel<<<nb_g1, G1_THREADS>>>(x, W1, n, ntiles);
    agg32_kernel<<<nb_w, 256>>>(b1, n);
    gemm2_kernel<<<nb_n, 256>>>(W2, n);
    agg16_kernel<<<nb_w, 256>>>(b2, out, n);
}

// round 17
// speedup vs baseline: 1.0583x; 1.0311x over previous
#include <cuda_runtime.h>
#include <cuda_fp16.h>
#include <stdint.h>

#define NMAX 100000
#define EMAX 3200000
#define H1 32
#define H2 16
#define IND 128
#define CAP 128            // slots per node; Poisson(32) tail @128 ~ 0
#define CAP_SHIFT 7

typedef unsigned long long u64;

// ---------------- scratch (device globals; no allocation allowed) ----------------
__device__ int     g_cnt[NMAX];
__device__ float   g_dinv[NMAX];
__device__ u64     g_slot[(size_t)NMAX * CAP];   // packed {w(f32)<<32 | src}
__device__ __half2 g_xw1h[NMAX * H1 / 2];        // dinv-prescaled x@W1, fp16
__device__ float   g_h[NMAX * H1];               // post layer-1 (relu), fp32
__device__ __half2 g_hw2h[NMAX * H2 / 2];        // dinv-prescaled h@W2, fp16

// ---------------- init ----------------
__global__ void zero_kernel(int n4) {
    int i = blockIdx.x * blockDim.x + threadIdx.x;
    if (i < n4) reinterpret_cast<int4*>(g_cnt)[i] = make_int4(0, 0, 0, 0);
}

// ---------------- single-pass scatter: count + place {w, src} ----------------
__global__ void scatter_kernel(const int* __restrict__ idx,
                               const float* __restrict__ w, int E) {
    int t = blockIdx.x * blockDim.x + threadIdx.x;
    int e = t * 2;
    if (e >= E) return;
    int2   s  = *reinterpret_cast<const int2*>(&idx[e]);
    int2   d  = *reinterpret_cast<const int2*>(&idx[E + e]);
    float2 wv = *reinterpret_cast<const float2*>(&w[e]);
    {
        int pos = atomicAdd(&g_cnt[d.x], 1);
        if (pos < CAP)
            g_slot[((size_t)d.x << CAP_SHIFT) + pos] =
                ((u64)(unsigned)__float_as_int(wv.x) << 32) | (unsigned)s.x;
    }
    if (e + 1 < E) {
        int pos = atomicAdd(&g_cnt[d.y], 1);
        if (pos < CAP)
            g_slot[((size_t)d.y << CAP_SHIFT) + pos] =
                ((u64)(unsigned)__float_as_int(wv.y) << 32) | (unsigned)s.y;
    }
}

// ---------------- deg reduce -> dinv (warp per node) ----------------
__global__ void dinv_kernel(int n) {
    int v = (blockIdx.x * blockDim.x + threadIdx.x) >> 5;
    int lane = threadIdx.x & 31;
    if (v >= n) return;
    int cnt = min(g_cnt[v], CAP);
    size_t base = (size_t)v << CAP_SHIFT;
    float s = 0.f;
    for (int i = lane; i < cnt; i += 32) {
        u64 p = __ldg(&g_slot[base + i]);
        s += __int_as_float((int)(p >> 32));
    }
    #pragma unroll
    for (int m = 16; m; m >>= 1) s += __shfl_xor_sync(0xffffffffu, s, m);
    if (lane == 0) g_dinv[v] = rsqrtf(s + 1.0f);
}

// ---------------- GEMM1: 2 threads per row, 16 cols each (R10 proven best) ----------
__global__ void __launch_bounds__(256) gemm1_kernel(const float* __restrict__ X,
                                                    const float* __restrict__ W, int n) {
    __shared__ float Ws[IND * H1];
    for (int i = threadIdx.x; i < IND * H1; i += blockDim.x) Ws[i] = W[i];
    __syncthreads();
    int g = blockIdx.x * blockDim.x + threadIdx.x;
    int r = g >> 1;            // row
    int half = g & 1;          // which 16 output cols
    if (r >= n) return;
    float acc[H1 / 2];
    #pragma unroll
    for (int j = 0; j < H1 / 2; j++) acc[j] = 0.f;
    const float4* X4 = reinterpret_cast<const float4*>(X) + (size_t)r * (IND / 4);
    int cbase = half * (H1 / 2);
    #pragma unroll 4
    for (int k4 = 0; k4 < IND / 4; k4++) {
        float4 xv = __ldg(&X4[k4]);   // paired lanes share the address -> coalesced
        float xk[4] = {xv.x, xv.y, xv.z, xv.w};
        #pragma unroll
        for (int kk = 0; kk < 4; kk++) {
            const float4* wr =
                reinterpret_cast<const float4*>(&Ws[(k4 * 4 + kk) * H1 + cbase]);
            float xs = xk[kk];
            #pragma unroll
            for (int j4 = 0; j4 < 4; j4++) {
                float4 wv = wr[j4];
                acc[4 * j4 + 0] = fmaf(xs, wv.x, acc[4 * j4 + 0]);
                acc[4 * j4 + 1] = fmaf(xs, wv.y, acc[4 * j4 + 1]);
                acc[4 * j4 + 2] = fmaf(xs, wv.z, acc[4 * j4 + 2]);
                acc[4 * j4 + 3] = fmaf(xs, wv.w, acc[4 * j4 + 3]);
            }
        }
    }
    float di = g_dinv[r];
    __half2* O = g_xw1h + (size_t)r * (H1 / 2) + half * (H1 / 4);
    #pragma unroll
    for (int j = 0; j < H1 / 4; j++)
        O[j] = __floats2half2_rn(acc[2 * j] * di, acc[2 * j + 1] * di);
}

// ---------------- agg layer 1: warp/node, 2 subs x 16 lanes x half2, unroll-2 ----------
__global__ void agg32_kernel(const float* __restrict__ b1, int n) {
    int v = (blockIdx.x * blockDim.x + threadIdx.x) >> 5;
    int lane = threadIdx.x & 31;
    if (v >= n) return;
    int sub = lane >> 4;          // 0/1: alternate edges
    int li  = lane & 15;          // half2 column
    size_t base = (size_t)v << CAP_SHIFT;
    int cnt = min(g_cnt[v], CAP);
    size_t end = base + cnt;
    float2 acc = make_float2(0.f, 0.f);
    size_t e = base + sub;
    for (; e + 2 < end; e += 4) {      // 2 edges in flight per sub
        u64 p0 = __ldg(&g_slot[e]);
        u64 p1 = __ldg(&g_slot[e + 2]);
        float w0 = __int_as_float((int)(p0 >> 32));
        float w1 = __int_as_float((int)(p1 >> 32));
        int s0 = (int)(p0 & 0xffffffffu);
        int s1 = (int)(p1 & 0xffffffffu);
        float2 f0 = __half22float2(__ldg(&g_xw1h[(size_t)s0 * 16 + li]));
        float2 f1 = __half22float2(__ldg(&g_xw1h[(size_t)s1 * 16 + li]));
        acc.x = fmaf(w0, f0.x, acc.x);
        acc.y = fmaf(w0, f0.y, acc.y);
        acc.x = fmaf(w1, f1.x, acc.x);
        acc.y = fmaf(w1, f1.y, acc.y);
    }
    for (; e < end; e += 2) {
        u64 p = __ldg(&g_slot[e]);
        float wv = __int_as_float((int)(p >> 32));
        int src = (int)(p & 0xffffffffu);
        float2 f = __half22float2(__ldg(&g_xw1h[(size_t)src * 16 + li]));
        acc.x = fmaf(wv, f.x, acc.x);
        acc.y = fmaf(wv, f.y, acc.y);
    }
    acc.x += __shfl_xor_sync(0xffffffffu, acc.x, 16);
    acc.y += __shfl_xor_sync(0xffffffffu, acc.y, 16);
    float di = g_dinv[v];
    float2 sf = __half22float2(__ldg(&g_xw1h[(size_t)v * 16 + li]));
    float2 r;
    r.x = fmaxf(fmaf(di, acc.x + sf.x, __ldg(&b1[2 * li])),     0.f);
    r.y = fmaxf(fmaf(di, acc.y + sf.y, __ldg(&b1[2 * li + 1])), 0.f);
    if (sub == 0)
        reinterpret_cast<float2*>(g_h)[(size_t)v * 16 + li] = r;
}

// ---------------- GEMM2: hw2h[r] = fp16( dinv[r] * (h[r] @ W2) ) ----------------
__global__ void gemm2_kernel(const float* __restrict__ W, int n) {
    __shared__ float Ws[H1 * H2];
    for (int i = threadIdx.x; i < H1 * H2; i += blockDim.x) Ws[i] = W[i];
    __syncthreads();
    int r = blockIdx.x * blockDim.x + threadIdx.x;
    if (r >= n) return;
    float acc[H2];
    #pragma unroll
    for (int j = 0; j < H2; j++) acc[j] = 0.f;
    const float4* X4 = reinterpret_cast<const float4*>(g_h) + (size_t)r * (H1 / 4);
    #pragma unroll
    for (int k4 = 0; k4 < H1 / 4; k4++) {
        float4 xv = X4[k4];
        float xk[4] = {xv.x, xv.y, xv.z, xv.w};
        #pragma unroll
        for (int kk = 0; kk < 4; kk++) {
            const float4* wr = reinterpret_cast<const float4*>(&Ws[(k4 * 4 + kk) * H2]);
            float xs = xk[kk];
            #pragma unroll
            for (int j4 = 0; j4 < H2 / 4; j4++) {
                float4 wv = wr[j4];
                acc[4 * j4 + 0] = fmaf(xs, wv.x, acc[4 * j4 + 0]);
                acc[4 * j4 + 1] = fmaf(xs, wv.y, acc[4 * j4 + 1]);
                acc[4 * j4 + 2] = fmaf(xs, wv.z, acc[4 * j4 + 2]);
                acc[4 * j4 + 3] = fmaf(xs, wv.w, acc[4 * j4 + 3]);
            }
        }
    }
    float di = g_dinv[r];
    __half2* O = g_hw2h + (size_t)r * (H2 / 2);
    #pragma unroll
    for (int j = 0; j < H2 / 2; j++)
        O[j] = __floats2half2_rn(acc[2 * j] * di, acc[2 * j + 1] * di);
}

// ---------------- agg layer 2: warp/node, 4 subs x 8 lanes x half2, unroll-2 ----------
__global__ void agg16_kernel(const float* __restrict__ b2, float* __restrict__ out, int n) {
    int v = (blockIdx.x * blockDim.x + threadIdx.x) >> 5;
    int lane = threadIdx.x & 31;
    if (v >= n) return;
    int sub = lane >> 3;          // 0..3: alternate edges
    int li  = lane & 7;           // half2 column
    size_t base = (size_t)v << CAP_SHIFT;
    int cnt = min(g_cnt[v], CAP);
    size_t end = base + cnt;
    float2 acc = make_float2(0.f, 0.f);
    size_t e = base + sub;
    for (; e + 4 < end; e += 8) {      // 2 edges in flight per sub
        u64 p0 = __ldg(&g_slot[e]);
        u64 p1 = __ldg(&g_slot[e + 4]);
        float w0 = __int_as_float((int)(p0 >> 32));
        float w1 = __int_as_float((int)(p1 >> 32));
        int s0 = (int)(p0 & 0xffffffffu);
        int s1 = (int)(p1 & 0xffffffffu);
        float2 f0 = __half22float2(__ldg(&g_hw2h[(size_t)s0 * 8 + li]));
        float2 f1 = __half22float2(__ldg(&g_hw2h[(size_t)s1 * 8 + li]));
        acc.x = fmaf(w0, f0.x, acc.x);
        acc.y = fmaf(w0, f0.y, acc.y);
        acc.x = fmaf(w1, f1.x, acc.x);
        acc.y = fmaf(w1, f1.y, acc.y);
    }
    for (; e < end; e += 4) {
        u64 p = __ldg(&g_slot[e]);
        float wv = __int_as_float((int)(p >> 32));
        int src = (int)(p & 0xffffffffu);
        float2 f = __half22float2(__ldg(&g_hw2h[(size_t)src * 8 + li]));
        acc.x = fmaf(wv, f.x, acc.x);
        acc.y = fmaf(wv, f.y, acc.y);
    }
    acc.x += __shfl_xor_sync(0xffffffffu, acc.x, 8);
    acc.y += __shfl_xor_sync(0xffffffffu, acc.y, 8);
    acc.x += __shfl_xor_sync(0xffffffffu, acc.x, 16);
    acc.y += __shfl_xor_sync(0xffffffffu, acc.y, 16);
    float di = g_dinv[v];
    float2 sf = __half22float2(__ldg(&g_hw2h[(size_t)v * 8 + li]));
    float2 r;
    r.x = fmaf(di, acc.x + sf.x, __ldg(&b2[2 * li]));
    r.y = fmaf(di, acc.y + sf.y, __ldg(&b2[2 * li + 1]));
    if (lane < 8)
        reinterpret_cast<float2*>(out)[(size_t)v * 8 + li] = r;
}

// ---------------- launch ----------------
extern "C" void kernel_launch(void* const* d_in, const int* in_sizes, int n_in,
                              void* d_out, int out_size) {
    const float* x   = (const float*)d_in[0];
    const int*   ei  = (const int*)d_in[1];
    const float* ew  = (const float*)d_in[2];
    const float* W1  = (const float*)d_in[3];
    const float* b1  = (const float*)d_in[4];
    const float* W2  = (const float*)d_in[5];
    const float* b2  = (const float*)d_in[6];
    float*       out = (float*)d_out;

    int E = in_sizes[2];
    int n = in_sizes[0] / IND;

    int n4 = (n + 3) / 4;
    int nb_n = (n + 255) / 256;
    int nb_e2 = ((E + 1) / 2 + 255) / 256;
    int nb_w = (n * 32 + 255) / 256;
    int nb_g1 = (2 * n + 255) / 256;

    zero_kernel<<<(n4 + 255) / 256, 256>>>(n4);
    scatter_kernel<<<nb_e2, 256>>>(ei, ew, E);
    dinv_kernel<<<nb_w, 256>>>(n);
    gemm1_kernel<<<nb_g1, 256>>>(x, W1, n);
    agg32_kernel<<<nb_w, 256>>>(b1, n);
    gemm2_kernel<<<nb_n, 256>>>(W2, n);
    agg16_kernel<<<nb_w, 256>>>(b2, out, n);
}